// round 7
// baseline (speedup 1.0000x reference)
#include <cuda_runtime.h>

#define NLAT_I 240
#define NLON_I 480
#define NLAT_O 361
#define NLON_O 720
#define CI     32
#define CO     32
#define KK     7
#define WOFF   10

#define PI_F      3.14159265358979323846f
#define TWO_PI_F  6.28318530717958647692f
#define CUTOFF_F  0.08508480103472356f
#define DR_F      0.028361600344907855f
#define DPH_F     2.0943951023931953f

typedef unsigned long long u64;

// ---------------- device scratch ----------------
static __device__ float g_xu4[8 * 361 * 720 * 4];                  // [g][t][p] float4 (ch 4g..4g+3)
static __device__ float g_psi8[(size_t)361 * 21 * 728 * 8];        // raw packed psi rows
static __device__ float g_sp[7 * 361 * 21];
static __device__ float g_invsc[7 * 361];
static __device__ float g_invs2[361 * 8];                          // per-t packed pair scales
static __device__ float g_w2[32 * 112 * 2];                        // packed weight pairs
static __device__ int   g_m[361 * 21];
static __device__ int   g_m2[361 * 21];

// ---------------- kernel A: bilinear upsample ----------------
__global__ void upsample_kernel(const float* __restrict__ x) {
    int idx = blockIdx.x * 256 + threadIdx.x;
    if (idx >= CI * NLAT_O * NLON_O) return;
    int p  = idx % NLON_O;
    int tt = (idx / NLON_O) % NLAT_O;
    int i  = idx / (NLON_O * NLAT_O);

    float theta = (float)tt * (PI_F / 360.0f);
    float post  = theta / (PI_F / 239.0f);
    float fi0 = floorf(post);
    int i0 = (int)fi0; i0 = min(max(i0, 0), NLAT_I - 1);
    int i1 = min(i0 + 1, NLAT_I - 1);
    float wt = post - (float)i0;

    float posp = ((float)p * (TWO_PI_F / (float)NLON_O)) / (TWO_PI_F / (float)NLON_I);
    float fj0 = floorf(posp);
    int j0 = ((int)fj0) % NLON_I;
    int j1 = j0 + 1; if (j1 >= NLON_I) j1 = 0;
    float wp = posp - fj0;

    const float* xi = x + i * (NLAT_I * NLON_I);
    float a  = xi[i0 * NLON_I + j0];
    float b  = xi[i0 * NLON_I + j1];
    float c  = xi[i1 * NLON_I + j0];
    float dv = xi[i1 * NLON_I + j1];
    float xl0 = (1.0f - wt) * a + wt * c;
    float xl1 = (1.0f - wt) * b + wt * dv;
    float val = (1.0f - wp) * xl0 + wp * xl1;

    g_xu4[(((i >> 2) * NLAT_O + tt) * NLON_O + p) * 4 + (i & 3)] = val;
}

// ---------------- kernel B: build packed psi + bounds ----------------
__global__ void build_psi_kernel() {
    int d = blockIdx.x;
    int t = blockIdx.y;
    int tid = threadIdx.x;

    int lt = t + d - WOFF;
    bool valid = (lt >= 0) && (lt <= NLAT_O - 1);
    int ltc = min(max(lt, 0), NLAT_O - 1);

    float tht = (float)t   * (PI_F / 360.0f);
    float thi = (float)ltc * (PI_F / 360.0f);
    float ca = cosf(tht), sa = sinf(tht);
    float cg = cosf(thi), sg = sinf(thi);
    float A = ca * cg;
    float B = sa * sg;
    float cosc = cosf(CUTOFF_F);

    int m;
    if (!valid)                 m = -1;
    else if (A - B >= cosc)     m = 360;
    else if (A + B <  cosc)     m = -1;
    else {
        float ratio = (cosc - A) / fmaxf(B, 1e-30f);
        ratio = fminf(fmaxf(ratio, -1.0f), 1.0f);
        m = (int)floorf(acosf(ratio) * (360.0f / PI_F)) + 2;
        if (m > 360) m = 360;
    }

    float cosc2i = cosf(2.0f * DR_F);
    float cosc2o = cosf(2.0f * DR_F + 1e-4f);
    int m2;
    if (m < 0)                   m2 = -1;
    else if (A - B >= cosc2i)    m2 = 360;
    else if (A + B <  cosc2o)    m2 = -1;
    else {
        float ratio = (cosc2o - A) / fmaxf(B, 1e-30f);
        ratio = fminf(fmaxf(ratio, -1.0f), 1.0f);
        m2 = (int)floorf(acosf(ratio) * (360.0f / PI_F)) + 3;
        if (m2 > 360) m2 = 360;
    }
    if (tid == 0) { g_m[t * 21 + d] = m; g_m2[t * 21 + d] = m2; }

    float dth = (float)(ltc - t) * (PI_F / 360.0f);
    float shd = sinf(0.5f * dth);
    float hav_lat = shd * shd;

    float sums[7] = {0.f, 0.f, 0.f, 0.f, 0.f, 0.f, 0.f};
    if (m >= 0) {
        float qfac = sg * (PI_F / 360.0f) * (PI_F / 360.0f);
        int cnt = 2 * m + 1;
        for (int s = tid; s < cnt; s += 256) {
            int pp = s - m; if (pp < 0) pp += NLON_O;
            float beta = (float)pp * (TWO_PI_F / (float)NLON_O);
            float cb = cosf(beta), sb = sinf(beta);
            float z = A + cb * B;
            z = fminf(fmaxf(z, -1.0f), 1.0f);
            float r_acos = acosf(z);
            float mask = (r_acos <= CUTOFF_F) ? qfac : 0.0f;
            float sbh = sinf(0.5f * beta);
            float h = hav_lat + B * sbh * sbh;
            float r = 2.0f * asinf(fminf(sqrtf(fmaxf(h, 0.0f)), 1.0f));

            float xx = ca * cb * sg - sa * cg;
            float yy = sb * sg;
            float phi = atan2f(yy, xx);
            if (phi < 0.0f) phi += TWO_PI_F;

            float v[7];
            v[0] = fmaxf(0.0f, 1.0f - r * (1.0f / DR_F)) * mask;
            #pragma unroll
            for (int k = 1; k < 7; ++k) {
                int ir = (k - 1) / 3 + 1;
                int ip = (k - 1) % 3;
                float rad = fmaxf(0.0f, 1.0f - fabsf(r - (float)ir * DR_F) * (1.0f / DR_F));
                float dd  = fabsf(phi - (float)ip * DPH_F);
                dd = fminf(dd, TWO_PI_F - dd);
                float az = fmaxf(0.0f, 1.0f - dd * (1.0f / DPH_F));
                v[k] = rad * az * mask;
            }
            size_t b8 = ((size_t)(t * 21 + d) * 728 + s) * 8;
            g_psi8[b8 + 0] = v[4];
            g_psi8[b8 + 1] = v[5];
            g_psi8[b8 + 2] = v[6];
            g_psi8[b8 + 3] = 0.0f;
            g_psi8[b8 + 4] = v[0];
            g_psi8[b8 + 5] = v[1];
            g_psi8[b8 + 6] = v[2];
            g_psi8[b8 + 7] = v[3];
            #pragma unroll
            for (int k = 0; k < 7; ++k) sums[k] += v[k];
        }
    }

    __shared__ float red[8][7];
    int lane = tid & 31, w = tid >> 5;
    #pragma unroll
    for (int k = 0; k < 7; ++k) {
        float s = sums[k];
        #pragma unroll
        for (int o = 16; o > 0; o >>= 1) s += __shfl_down_sync(0xffffffffu, s, o);
        if (lane == 0) red[w][k] = s;
    }
    __syncthreads();
    if (tid < 7) {
        float s = 0.0f;
        #pragma unroll
        for (int ww = 0; ww < 8; ++ww) s += red[ww][tid];
        g_sp[(tid * 361 + t) * 21 + d] = s;
    }
}

// ---------------- kernel INV ----------------
__global__ void inv_kernel() {
    int i = blockIdx.x * blockDim.x + threadIdx.x;
    if (i < 7 * 361) {
        float s = 0.0f;
        #pragma unroll
        for (int d = 0; d < 21; ++d) s += g_sp[i * 21 + d];
        g_invsc[i] = 1.0f / fmaxf(s, 1e-8f);
    }
}

// ---------------- kernel PACK: weight pairs + per-t scale pairs ----------------
__global__ void pack_kernel(const float* __restrict__ wgt) {
    int idx = blockIdx.x * 256 + threadIdx.x;
    if (idx < 32 * 112) {
        int o = idx / 112;
        int j = idx - o * 112;
        int k = j >> 4;
        int h = j & 15;
        g_w2[idx * 2 + 0] = wgt[(o * CI + 2 * h) * KK + k];
        g_w2[idx * 2 + 1] = wgt[(o * CI + 2 * h + 1) * KK + k];
    }
    if (idx < 361) {
        float iv[7];
        #pragma unroll
        for (int k = 0; k < 7; ++k) iv[k] = g_invsc[k * 361 + idx];
        g_invs2[idx * 8 + 0] = iv[4];
        g_invs2[idx * 8 + 1] = iv[5];
        g_invs2[idx * 8 + 2] = iv[6];
        g_invs2[idx * 8 + 3] = 0.0f;
        g_invs2[idx * 8 + 4] = iv[0];
        g_invs2[idx * 8 + 5] = iv[1];
        g_invs2[idx * 8 + 6] = iv[2];
        g_invs2[idx * 8 + 7] = iv[3];
    }
}

// ---------------- kernel C: conv + fused GEMM ----------------
// phase1 smem: xu float4[8][720] (92160B) + psi float[728][8] (23296B) = 115456B
// phase2 (aliased): z2 float[112][32][2] (28672B)
#define SMEM_C (8 * 720 * 16 + 728 * 8 * 4)

#define DUPS(xv)                                                   \
    u64 d0, d1, d2, d3;                                            \
    asm("mov.b64 %0,{%1,%1};" : "=l"(d0) : "f"(xv.x));             \
    asm("mov.b64 %0,{%1,%1};" : "=l"(d1) : "f"(xv.y));             \
    asm("mov.b64 %0,{%1,%1};" : "=l"(d2) : "f"(xv.z));             \
    asm("mov.b64 %0,{%1,%1};" : "=l"(d3) : "f"(xv.w));

#define BODY4(XV, SS) {                                            \
    float4 xv = (XV);                                              \
    u64 pA, pB, pC, pD;                                            \
    asm("ld.shared.v2.u64 {%0,%1},[%2];" : "=l"(pA), "=l"(pB)      \
        : "r"(psi_u + (unsigned)(SS) * 32u));                      \
    asm("ld.shared.v2.u64 {%0,%1},[%2];" : "=l"(pC), "=l"(pD)      \
        : "r"(psi_u + (unsigned)(SS) * 32u + 16u));                \
    DUPS(xv)                                                       \
    asm("fma.rn.f32x2 %0,%1,%2,%0;" : "+l"(aA[0]) : "l"(pA), "l"(d0)); \
    asm("fma.rn.f32x2 %0,%1,%2,%0;" : "+l"(aB[0]) : "l"(pB), "l"(d0)); \
    asm("fma.rn.f32x2 %0,%1,%2,%0;" : "+l"(aC[0]) : "l"(pC), "l"(d0)); \
    asm("fma.rn.f32x2 %0,%1,%2,%0;" : "+l"(aD[0]) : "l"(pD), "l"(d0)); \
    asm("fma.rn.f32x2 %0,%1,%2,%0;" : "+l"(aA[1]) : "l"(pA), "l"(d1)); \
    asm("fma.rn.f32x2 %0,%1,%2,%0;" : "+l"(aB[1]) : "l"(pB), "l"(d1)); \
    asm("fma.rn.f32x2 %0,%1,%2,%0;" : "+l"(aC[1]) : "l"(pC), "l"(d1)); \
    asm("fma.rn.f32x2 %0,%1,%2,%0;" : "+l"(aD[1]) : "l"(pD), "l"(d1)); \
    asm("fma.rn.f32x2 %0,%1,%2,%0;" : "+l"(aA[2]) : "l"(pA), "l"(d2)); \
    asm("fma.rn.f32x2 %0,%1,%2,%0;" : "+l"(aB[2]) : "l"(pB), "l"(d2)); \
    asm("fma.rn.f32x2 %0,%1,%2,%0;" : "+l"(aC[2]) : "l"(pC), "l"(d2)); \
    asm("fma.rn.f32x2 %0,%1,%2,%0;" : "+l"(aD[2]) : "l"(pD), "l"(d2)); \
    asm("fma.rn.f32x2 %0,%1,%2,%0;" : "+l"(aA[3]) : "l"(pA), "l"(d3)); \
    asm("fma.rn.f32x2 %0,%1,%2,%0;" : "+l"(aB[3]) : "l"(pB), "l"(d3)); \
    asm("fma.rn.f32x2 %0,%1,%2,%0;" : "+l"(aC[3]) : "l"(pC), "l"(d3)); \
    asm("fma.rn.f32x2 %0,%1,%2,%0;" : "+l"(aD[3]) : "l"(pD), "l"(d3)); }

#define BODY2(XV, SS) {                                            \
    float4 xv = (XV);                                              \
    u64 pA, pB;                                                    \
    asm("ld.shared.v2.u64 {%0,%1},[%2];" : "=l"(pA), "=l"(pB)      \
        : "r"(psi_u + (unsigned)(SS) * 32u));                      \
    DUPS(xv)                                                       \
    asm("fma.rn.f32x2 %0,%1,%2,%0;" : "+l"(aA[0]) : "l"(pA), "l"(d0)); \
    asm("fma.rn.f32x2 %0,%1,%2,%0;" : "+l"(aB[0]) : "l"(pB), "l"(d0)); \
    asm("fma.rn.f32x2 %0,%1,%2,%0;" : "+l"(aA[1]) : "l"(pA), "l"(d1)); \
    asm("fma.rn.f32x2 %0,%1,%2,%0;" : "+l"(aB[1]) : "l"(pB), "l"(d1)); \
    asm("fma.rn.f32x2 %0,%1,%2,%0;" : "+l"(aA[2]) : "l"(pA), "l"(d2)); \
    asm("fma.rn.f32x2 %0,%1,%2,%0;" : "+l"(aB[2]) : "l"(pB), "l"(d2)); \
    asm("fma.rn.f32x2 %0,%1,%2,%0;" : "+l"(aA[3]) : "l"(pA), "l"(d3)); \
    asm("fma.rn.f32x2 %0,%1,%2,%0;" : "+l"(aB[3]) : "l"(pB), "l"(d3)); }

__global__ void __launch_bounds__(256, 2)
conv_kernel(float* __restrict__ y) {
    extern __shared__ float sm[];
    float4* xu_s  = (float4*)sm;                        // [8][720]
    float*  psi_s = sm + 8 * 720 * 4;                   // [728][8]
    unsigned psi_u = (unsigned)__cvta_generic_to_shared(psi_s);

    int ty = blockIdx.y;
    int t  = (ty & 1) ? (360 - (ty >> 1)) : (ty >> 1);  // heavy rows first
    int p0 = blockIdx.x * 32;
    int tid  = threadIdx.x;
    int lane = tid & 31;
    int ig   = tid >> 5;                                // warp -> channels 4ig..4ig+3

    u64 aA[4], aB[4], aC[4], aD[4];
    #pragma unroll
    for (int c = 0; c < 4; ++c) { aA[c] = 0ull; aB[c] = 0ull; aC[c] = 0ull; aD[c] = 0ull; }

    const float4* gx4 = (const float4*)g_xu4;

    for (int d = 0; d < 21; ++d) {
        int lt = t + d - WOFF;
        if (lt < 0 || lt > 360) continue;
        int m = g_m[t * 21 + d];
        if (m < 0) continue;
        int m2 = g_m2[t * 21 + d];
        int cnt = 2 * m + 1;
        int L = 32 + 2 * m;
        int n = (L < 720) ? L : 720;
        int base = p0 - m;
        base %= 720; if (base < 0) base += 720;
        int iA, iB;
        if (m2 < 0) { iA = cnt; iB = cnt; }
        else { iA = max(0, m - m2); iB = min(cnt, m + m2 + 1); }

        __syncthreads();
        // stage xu window: warp ig handles group ig
        {
            const float4* src = gx4 + ((size_t)ig * NLAT_O + lt) * NLON_O;
            for (int q = lane; q < n; q += 32) {
                int lon = base + q; if (lon >= 720) lon -= 720;
                xu_s[ig * 720 + q] = src[lon];
            }
        }
        // stage psi (pure copy)
        {
            const float4* src = (const float4*)(g_psi8 + ((size_t)(t * 21 + d)) * 728 * 8);
            float4* dst = (float4*)psi_s;
            for (int s2 = tid; s2 < 2 * cnt; s2 += 256) dst[s2] = src[s2];
        }
        __syncthreads();

        const float4* xl = xu_s + ig * 720 + lane;
        int s = 0;
        if (m <= 343) {
            // wrap-free: q = s + lane < n <= 720 always
            #pragma unroll 2
            for (; s < iA; ++s) BODY2(xl[s], s);
            #pragma unroll 2
            for (; s < iB; ++s) BODY4(xl[s], s);
            #pragma unroll 2
            for (; s < cnt; ++s) BODY2(xl[s], s);
        } else {
            const float4* xa = xu_s + ig * 720;
            int q = lane;
            #pragma unroll 2
            for (; s < iA; ++s) { BODY2(xa[q], s); ++q; if (q >= 720) q -= 720; }
            #pragma unroll 2
            for (; s < iB; ++s) { BODY4(xa[q], s); ++q; if (q >= 720) q -= 720; }
            #pragma unroll 2
            for (; s < cnt; ++s) { BODY2(xa[q], s); ++q; if (q >= 720) q -= 720; }
        }
    }

    __syncthreads();
    // ---- phase 2: fold scales, scatter z, GEMM with ldg'd weight pairs ----
    {
        const u64* ivp = (const u64*)(g_invs2 + t * 8);
        u64 iv0 = ivp[0], iv1 = ivp[1], iv2 = ivp[2], iv3 = ivp[3];
        #pragma unroll
        for (int c = 0; c < 4; ++c) {
            asm("mul.rn.f32x2 %0,%0,%1;" : "+l"(aA[c]) : "l"(iv0));
            asm("mul.rn.f32x2 %0,%0,%1;" : "+l"(aB[c]) : "l"(iv1));
            asm("mul.rn.f32x2 %0,%0,%1;" : "+l"(aC[c]) : "l"(iv2));
            asm("mul.rn.f32x2 %0,%0,%1;" : "+l"(aD[c]) : "l"(iv3));
        }
    }

    float* z2f = sm;                        // [112][32][2] floats
    {
        int ibase = 4 * ig;
        #pragma unroll
        for (int c = 0; c < 4; ++c) {
            int i = ibase + c;
            int half = i >> 1, par = i & 1;
            float lo, hi;
            asm("mov.b64 {%0,%1},%2;" : "=f"(lo), "=f"(hi) : "l"(aA[c]));
            z2f[(((4 * 16 + half) * 32 + lane) * 2) + par] = lo;
            z2f[(((5 * 16 + half) * 32 + lane) * 2) + par] = hi;
            asm("mov.b64 {%0,%1},%2;" : "=f"(lo), "=f"(hi) : "l"(aB[c]));
            z2f[(((6 * 16 + half) * 32 + lane) * 2) + par] = lo;
            asm("mov.b64 {%0,%1},%2;" : "=f"(lo), "=f"(hi) : "l"(aC[c]));
            z2f[(((0 * 16 + half) * 32 + lane) * 2) + par] = lo;
            z2f[(((1 * 16 + half) * 32 + lane) * 2) + par] = hi;
            asm("mov.b64 {%0,%1},%2;" : "=f"(lo), "=f"(hi) : "l"(aD[c]));
            z2f[(((2 * 16 + half) * 32 + lane) * 2) + par] = lo;
            z2f[(((3 * 16 + half) * 32 + lane) * 2) + par] = hi;
        }
    }
    __syncthreads();

    const u64* z2u = (const u64*)z2f;
    const u64* w2u = (const u64*)g_w2;
    u64 acc2[4];
    #pragma unroll
    for (int oo = 0; oo < 4; ++oo) acc2[oo] = 0ull;

    #pragma unroll 4
    for (int j = 0; j < 112; ++j) {
        u64 zp = z2u[j * 32 + lane];
        #pragma unroll
        for (int oo = 0; oo < 4; ++oo) {
            u64 wv = __ldg(w2u + (ig + 8 * oo) * 112 + j);
            asm("fma.rn.f32x2 %0,%1,%2,%0;" : "+l"(acc2[oo]) : "l"(wv), "l"(zp));
        }
    }

    int p = p0 + lane;
    if (p < 720) {
        #pragma unroll
        for (int oo = 0; oo < 4; ++oo) {
            int o = ig + 8 * oo;
            float lo, hi;
            asm("mov.b64 {%0,%1},%2;" : "=f"(lo), "=f"(hi) : "l"(acc2[oo]));
            y[((size_t)o * NLAT_O + t) * NLON_O + p] = lo + hi;
        }
    }
}

// ---------------- launcher ----------------
extern "C" void kernel_launch(void* const* d_in, const int* in_sizes, int n_in,
                              void* d_out, int out_size) {
    const float* x = (const float*)d_in[0];       // [1,32,240,480]
    const float* w = (const float*)d_in[1];       // [32,32,7]
    float* y = (float*)d_out;                     // [1,32,361,720]

    cudaFuncSetAttribute(conv_kernel, cudaFuncAttributeMaxDynamicSharedMemorySize, SMEM_C);

    int nA = CI * NLAT_O * NLON_O;
    upsample_kernel<<<(nA + 255) / 256, 256>>>(x);
    build_psi_kernel<<<dim3(21, 361), 256>>>();
    inv_kernel<<<(7 * 361 + 255) / 256, 256>>>();
    pack_kernel<<<(32 * 112 + 255) / 256, 256>>>(w);
    conv_kernel<<<dim3(23, 361), 256, SMEM_C>>>(y);
}

// round 8
// speedup vs baseline: 1.2240x; 1.2240x over previous
#include <cuda_runtime.h>

#define NLAT_I 240
#define NLON_I 480
#define NLAT_O 361
#define NLON_O 720
#define CI     32
#define CO     32
#define KK     7
#define WOFF   10

#define PI_F      3.14159265358979323846f
#define TWO_PI_F  6.28318530717958647692f
#define CUTOFF_F  0.08508480103472356f
#define DR_F      0.028361600344907855f
#define DPH_F     2.0943951023931953f

typedef unsigned long long u64;

// ---------------- device scratch ----------------
static __device__ float g_xu4[8 * 361 * 720 * 4];                  // [g][t][p] float4 (ch 4g..4g+3)
static __device__ float g_psi8[(size_t)361 * 21 * 728 * 8];        // packed psi rows
static __device__ float g_sp[7 * 361 * 21];
static __device__ float g_invsc[7 * 361];
static __device__ float g_invs2[361 * 8];                          // per-t packed pair scales
static __device__ float g_w2[32 * 112 * 2];                        // packed weight pairs
static __device__ int   g_m[361 * 21];
static __device__ int   g_m2[361 * 21];

// ---------------- kernel A: bilinear upsample ----------------
__global__ void upsample_kernel(const float* __restrict__ x) {
    int idx = blockIdx.x * 256 + threadIdx.x;
    if (idx >= CI * NLAT_O * NLON_O) return;
    int p  = idx % NLON_O;
    int tt = (idx / NLON_O) % NLAT_O;
    int i  = idx / (NLON_O * NLAT_O);

    float theta = (float)tt * (PI_F / 360.0f);
    float post  = theta / (PI_F / 239.0f);
    float fi0 = floorf(post);
    int i0 = (int)fi0; i0 = min(max(i0, 0), NLAT_I - 1);
    int i1 = min(i0 + 1, NLAT_I - 1);
    float wt = post - (float)i0;

    float posp = ((float)p * (TWO_PI_F / (float)NLON_O)) / (TWO_PI_F / (float)NLON_I);
    float fj0 = floorf(posp);
    int j0 = ((int)fj0) % NLON_I;
    int j1 = j0 + 1; if (j1 >= NLON_I) j1 = 0;
    float wp = posp - fj0;

    const float* xi = x + i * (NLAT_I * NLON_I);
    float a  = xi[i0 * NLON_I + j0];
    float b  = xi[i0 * NLON_I + j1];
    float c  = xi[i1 * NLON_I + j0];
    float dv = xi[i1 * NLON_I + j1];
    float xl0 = (1.0f - wt) * a + wt * c;
    float xl1 = (1.0f - wt) * b + wt * dv;
    float val = (1.0f - wp) * xl0 + wp * xl1;

    g_xu4[(((i >> 2) * NLAT_O + tt) * NLON_O + p) * 4 + (i & 3)] = val;
}

// ---------------- kernel B: build packed psi + bounds ----------------
__global__ void build_psi_kernel() {
    int d = blockIdx.x;
    int t = blockIdx.y;
    int tid = threadIdx.x;

    int lt = t + d - WOFF;
    bool valid = (lt >= 0) && (lt <= NLAT_O - 1);
    int ltc = min(max(lt, 0), NLAT_O - 1);

    float tht = (float)t   * (PI_F / 360.0f);
    float thi = (float)ltc * (PI_F / 360.0f);
    float ca = cosf(tht), sa = sinf(tht);
    float cg = cosf(thi), sg = sinf(thi);
    float A = ca * cg;
    float B = sa * sg;
    float cosc = cosf(CUTOFF_F);

    int m;
    if (!valid)                 m = -1;
    else if (A - B >= cosc)     m = 360;
    else if (A + B <  cosc)     m = -1;
    else {
        float ratio = (cosc - A) / fmaxf(B, 1e-30f);
        ratio = fminf(fmaxf(ratio, -1.0f), 1.0f);
        m = (int)floorf(acosf(ratio) * (360.0f / PI_F)) + 2;
        if (m > 360) m = 360;
    }

    float cosc2i = cosf(2.0f * DR_F);
    float cosc2o = cosf(2.0f * DR_F + 1e-4f);
    int m2;
    if (m < 0)                   m2 = -1;
    else if (A - B >= cosc2i)    m2 = 360;
    else if (A + B <  cosc2o)    m2 = -1;
    else {
        float ratio = (cosc2o - A) / fmaxf(B, 1e-30f);
        ratio = fminf(fmaxf(ratio, -1.0f), 1.0f);
        m2 = (int)floorf(acosf(ratio) * (360.0f / PI_F)) + 3;
        if (m2 > 360) m2 = 360;
    }
    if (tid == 0) { g_m[t * 21 + d] = m; g_m2[t * 21 + d] = m2; }

    float dth = (float)(ltc - t) * (PI_F / 360.0f);
    float shd = sinf(0.5f * dth);
    float hav_lat = shd * shd;

    float sums[7] = {0.f, 0.f, 0.f, 0.f, 0.f, 0.f, 0.f};
    if (m >= 0) {
        float qfac = sg * (PI_F / 360.0f) * (PI_F / 360.0f);
        int cnt = 2 * m + 1;
        for (int s = tid; s < cnt; s += 256) {
            int pp = s - m; if (pp < 0) pp += NLON_O;
            float beta = (float)pp * (TWO_PI_F / (float)NLON_O);
            float cb = cosf(beta), sb = sinf(beta);
            float z = A + cb * B;
            z = fminf(fmaxf(z, -1.0f), 1.0f);
            float r_acos = acosf(z);
            float mask = (r_acos <= CUTOFF_F) ? qfac : 0.0f;
            float sbh = sinf(0.5f * beta);
            float h = hav_lat + B * sbh * sbh;
            float r = 2.0f * asinf(fminf(sqrtf(fmaxf(h, 0.0f)), 1.0f));

            float xx = ca * cb * sg - sa * cg;
            float yy = sb * sg;
            float phi = atan2f(yy, xx);
            if (phi < 0.0f) phi += TWO_PI_F;

            float v[7];
            v[0] = fmaxf(0.0f, 1.0f - r * (1.0f / DR_F)) * mask;
            #pragma unroll
            for (int k = 1; k < 7; ++k) {
                int ir = (k - 1) / 3 + 1;
                int ip = (k - 1) % 3;
                float rad = fmaxf(0.0f, 1.0f - fabsf(r - (float)ir * DR_F) * (1.0f / DR_F));
                float dd  = fabsf(phi - (float)ip * DPH_F);
                dd = fminf(dd, TWO_PI_F - dd);
                float az = fmaxf(0.0f, 1.0f - dd * (1.0f / DPH_F));
                v[k] = rad * az * mask;
            }
            size_t b8 = ((size_t)(t * 21 + d) * 728 + s) * 8;
            g_psi8[b8 + 0] = v[4];
            g_psi8[b8 + 1] = v[5];
            g_psi8[b8 + 2] = v[6];
            g_psi8[b8 + 3] = 0.0f;
            g_psi8[b8 + 4] = v[0];
            g_psi8[b8 + 5] = v[1];
            g_psi8[b8 + 6] = v[2];
            g_psi8[b8 + 7] = v[3];
            #pragma unroll
            for (int k = 0; k < 7; ++k) sums[k] += v[k];
        }
    }

    __shared__ float red[8][7];
    int lane = tid & 31, w = tid >> 5;
    #pragma unroll
    for (int k = 0; k < 7; ++k) {
        float s = sums[k];
        #pragma unroll
        for (int o = 16; o > 0; o >>= 1) s += __shfl_down_sync(0xffffffffu, s, o);
        if (lane == 0) red[w][k] = s;
    }
    __syncthreads();
    if (tid < 7) {
        float s = 0.0f;
        #pragma unroll
        for (int ww = 0; ww < 8; ++ww) s += red[ww][tid];
        g_sp[(tid * 361 + t) * 21 + d] = s;
    }
}

// ---------------- kernel INV ----------------
__global__ void inv_kernel() {
    int i = blockIdx.x * blockDim.x + threadIdx.x;
    if (i < 7 * 361) {
        float s = 0.0f;
        #pragma unroll
        for (int d = 0; d < 21; ++d) s += g_sp[i * 21 + d];
        g_invsc[i] = 1.0f / fmaxf(s, 1e-8f);
    }
}

// ---------------- kernel PACK ----------------
__global__ void pack_kernel(const float* __restrict__ wgt) {
    int idx = blockIdx.x * 256 + threadIdx.x;
    if (idx < 32 * 112) {
        int o = idx / 112;
        int j = idx - o * 112;
        int k = j >> 4;
        int h = j & 15;
        g_w2[idx * 2 + 0] = wgt[(o * CI + 2 * h) * KK + k];
        g_w2[idx * 2 + 1] = wgt[(o * CI + 2 * h + 1) * KK + k];
    }
    if (idx < 361) {
        float iv[7];
        #pragma unroll
        for (int k = 0; k < 7; ++k) iv[k] = g_invsc[k * 361 + idx];
        g_invs2[idx * 8 + 0] = iv[4];
        g_invs2[idx * 8 + 1] = iv[5];
        g_invs2[idx * 8 + 2] = iv[6];
        g_invs2[idx * 8 + 3] = 0.0f;
        g_invs2[idx * 8 + 4] = iv[0];
        g_invs2[idx * 8 + 5] = iv[1];
        g_invs2[idx * 8 + 6] = iv[2];
        g_invs2[idx * 8 + 7] = iv[3];
    }
}

// ---------------- kernel C: conv + fused GEMM (64-wide p-tile, 8 ch/warp) ----------------
// phase1 smem: xu float4[8][720] (92160B) + psi float[728][8] (23296B) = 115456B
// phase2 (aliased): z2 float[112][64][2] (57344B) + w2s float[32*112*2] (28672B) = 86016B
#define SMEM_C (8 * 720 * 16 + 728 * 8 * 4)

#define FMA8(V, C)                                                       \
    { u64 du;                                                            \
      asm("mov.b64 %0,{%1,%1};" : "=l"(du) : "f"(V));                    \
      asm("fma.rn.f32x2 %0,%1,%2,%0;" : "+l"(aA[C]) : "l"(pA), "l"(du)); \
      asm("fma.rn.f32x2 %0,%1,%2,%0;" : "+l"(aB[C]) : "l"(pB), "l"(du)); \
      asm("fma.rn.f32x2 %0,%1,%2,%0;" : "+l"(aC[C]) : "l"(pC), "l"(du)); \
      asm("fma.rn.f32x2 %0,%1,%2,%0;" : "+l"(aD[C]) : "l"(pD), "l"(du)); }

#define FMA4(V, C)                                                       \
    { u64 du;                                                            \
      asm("mov.b64 %0,{%1,%1};" : "=l"(du) : "f"(V));                    \
      asm("fma.rn.f32x2 %0,%1,%2,%0;" : "+l"(aA[C]) : "l"(pA), "l"(du)); \
      asm("fma.rn.f32x2 %0,%1,%2,%0;" : "+l"(aB[C]) : "l"(pB), "l"(du)); }

#define BODY4(Q, SS) {                                                   \
    float4 x0 = xq0[Q];                                                  \
    float4 x1 = xq1[Q];                                                  \
    u64 pA, pB, pC, pD;                                                  \
    asm("ld.shared.v2.u64 {%0,%1},[%2];" : "=l"(pA), "=l"(pB)            \
        : "r"(psi_u + (unsigned)(SS) * 32u));                            \
    asm("ld.shared.v2.u64 {%0,%1},[%2];" : "=l"(pC), "=l"(pD)            \
        : "r"(psi_u + (unsigned)(SS) * 32u + 16u));                      \
    FMA8(x0.x, 0) FMA8(x0.y, 1) FMA8(x0.z, 2) FMA8(x0.w, 3)              \
    FMA8(x1.x, 4) FMA8(x1.y, 5) FMA8(x1.z, 6) FMA8(x1.w, 7) }

#define BODY2(Q, SS) {                                                   \
    float4 x0 = xq0[Q];                                                  \
    float4 x1 = xq1[Q];                                                  \
    u64 pA, pB;                                                          \
    asm("ld.shared.v2.u64 {%0,%1},[%2];" : "=l"(pA), "=l"(pB)            \
        : "r"(psi_u + (unsigned)(SS) * 32u));                            \
    FMA4(x0.x, 0) FMA4(x0.y, 1) FMA4(x0.z, 2) FMA4(x0.w, 3)              \
    FMA4(x1.x, 4) FMA4(x1.y, 5) FMA4(x1.z, 6) FMA4(x1.w, 7) }

__global__ void __launch_bounds__(256, 2)
conv_kernel(float* __restrict__ y) {
    extern __shared__ float sm[];
    float4* xu_s  = (float4*)sm;                        // [8][720]
    float*  psi_s = sm + 8 * 720 * 4;                   // [728][8]
    unsigned psi_u = (unsigned)__cvta_generic_to_shared(psi_s);

    int ty = blockIdx.y;
    int t  = (ty & 1) ? (360 - (ty >> 1)) : (ty >> 1);  // heavy rows first
    int p0 = blockIdx.x * 64;
    int tid  = threadIdx.x;
    int lane = tid & 31;
    int wpi  = tid >> 5;
    int sub  = wpi & 1;                                 // p-subtile (0..1)
    int cg   = wpi >> 1;                                // channel octet (0..3)

    u64 aA[8], aB[8], aC[8], aD[8];
    #pragma unroll
    for (int c = 0; c < 8; ++c) { aA[c] = 0ull; aB[c] = 0ull; aC[c] = 0ull; aD[c] = 0ull; }

    const float4* gx4 = (const float4*)g_xu4;

    for (int d = 0; d < 21; ++d) {
        int lt = t + d - WOFF;
        if (lt < 0 || lt > 360) continue;
        int m = g_m[t * 21 + d];
        if (m < 0) continue;
        int m2 = g_m2[t * 21 + d];
        int cnt = 2 * m + 1;
        int L = 64 + 2 * m;
        int n = (L < 720) ? L : 720;
        int base = p0 - m;
        base %= 720; if (base < 0) base += 720;
        int iA, iB;
        if (m2 < 0) { iA = cnt; iB = cnt; }
        else { iA = max(0, m - m2); iB = min(cnt, m + m2 + 1); }

        __syncthreads();
        // stage xu window: warp wpi stages group wpi
        {
            const float4* src = gx4 + ((size_t)wpi * NLAT_O + lt) * NLON_O;
            for (int q = lane; q < n; q += 32) {
                int lon = base + q; if (lon >= 720) lon -= 720;
                xu_s[wpi * 720 + q] = src[lon];
            }
        }
        // stage psi (pure copy)
        {
            const float4* src = (const float4*)(g_psi8 + ((size_t)(t * 21 + d)) * 728 * 8);
            float4* dst = (float4*)psi_s;
            for (int s2 = tid; s2 < 2 * cnt; s2 += 256) dst[s2] = src[s2];
        }
        __syncthreads();

        const float4* xq0 = xu_s + (2 * cg) * 720;
        const float4* xq1 = xq0 + 720;
        int qb = 32 * sub + lane;
        int s = 0;
        if (n < 720) {
            // wrap-free: qb + s <= 63 + 2m = n-1
            const float4* xa0 = xq0 + qb;
            const float4* xa1 = xq1 + qb;
            const float4* xq0 = xa0;   // shadow for macro
            const float4* xq1 = xa1;
            for (; s < iA; ++s) BODY2(s, s);
            for (; s < iB; ++s) BODY4(s, s);
            for (; s < cnt; ++s) BODY2(s, s);
        } else {
            int q = qb;
            for (; s < iA; ++s) { BODY2(q, s); ++q; if (q >= 720) q -= 720; }
            for (; s < iB; ++s) { BODY4(q, s); ++q; if (q >= 720) q -= 720; }
            for (; s < cnt; ++s) { BODY2(q, s); ++q; if (q >= 720) q -= 720; }
        }
    }

    __syncthreads();
    // ---- fold scales ----
    {
        const u64* ivp = (const u64*)(g_invs2 + t * 8);
        u64 iv0 = ivp[0], iv1 = ivp[1], iv2 = ivp[2], iv3 = ivp[3];
        #pragma unroll
        for (int c = 0; c < 8; ++c) {
            asm("mul.rn.f32x2 %0,%0,%1;" : "+l"(aA[c]) : "l"(iv0));
            asm("mul.rn.f32x2 %0,%0,%1;" : "+l"(aB[c]) : "l"(iv1));
            asm("mul.rn.f32x2 %0,%0,%1;" : "+l"(aC[c]) : "l"(iv2));
            asm("mul.rn.f32x2 %0,%0,%1;" : "+l"(aD[c]) : "l"(iv3));
        }
    }

    // ---- phase 2: scatter z [112][64][2], stage w, GEMM ----
    float* z2f = sm;                                 // 14336 floats
    float* w2s = sm + 112 * 64 * 2;                  // 7168 floats
    {
        int pcol = 32 * sub + lane;
        #pragma unroll
        for (int c = 0; c < 8; ++c) {
            int i = 8 * cg + c;
            int half = i >> 1, par = i & 1;
            float lo, hi;
            asm("mov.b64 {%0,%1},%2;" : "=f"(lo), "=f"(hi) : "l"(aA[c]));
            z2f[(((4 * 16 + half) * 64 + pcol) * 2) + par] = lo;
            z2f[(((5 * 16 + half) * 64 + pcol) * 2) + par] = hi;
            asm("mov.b64 {%0,%1},%2;" : "=f"(lo), "=f"(hi) : "l"(aB[c]));
            z2f[(((6 * 16 + half) * 64 + pcol) * 2) + par] = lo;
            asm("mov.b64 {%0,%1},%2;" : "=f"(lo), "=f"(hi) : "l"(aC[c]));
            z2f[(((0 * 16 + half) * 64 + pcol) * 2) + par] = lo;
            z2f[(((1 * 16 + half) * 64 + pcol) * 2) + par] = hi;
            asm("mov.b64 {%0,%1},%2;" : "=f"(lo), "=f"(hi) : "l"(aD[c]));
            z2f[(((2 * 16 + half) * 64 + pcol) * 2) + par] = lo;
            z2f[(((3 * 16 + half) * 64 + pcol) * 2) + par] = hi;
        }
    }
    // stage weight pairs to smem (7168 floats = 1792 float4)
    {
        const float4* src = (const float4*)g_w2;
        float4* dst = (float4*)w2s;
        for (int i = tid; i < 1792; i += 256) dst[i] = src[i];
    }
    __syncthreads();

    // GEMM: thread = 2 adjacent p x 4 o
    int po2 = tid & 31;            // p pair index
    int og  = (tid >> 5) & 7;      // o = og + 8*oo
    const ulonglong2* zp = (const ulonglong2*)z2f;   // [112][32] pairs of u64
    const u64* wu = (const u64*)w2s;

    u64 acc0[4], acc1[4];
    #pragma unroll
    for (int oo = 0; oo < 4; ++oo) { acc0[oo] = 0ull; acc1[oo] = 0ull; }

    for (int j = 0; j < 112; ++j) {
        ulonglong2 zv = zp[j * 32 + po2];
        #pragma unroll
        for (int oo = 0; oo < 4; ++oo) {
            u64 wv = wu[(og + 8 * oo) * 112 + j];
            asm("fma.rn.f32x2 %0,%1,%2,%0;" : "+l"(acc0[oo]) : "l"(wv), "l"(zv.x));
            asm("fma.rn.f32x2 %0,%1,%2,%0;" : "+l"(acc1[oo]) : "l"(wv), "l"(zv.y));
        }
    }

    int pA0 = p0 + 2 * po2;
    int pA1 = pA0 + 1;
    #pragma unroll
    for (int oo = 0; oo < 4; ++oo) {
        int o = og + 8 * oo;
        float lo, hi;
        if (pA0 < 720) {
            asm("mov.b64 {%0,%1},%2;" : "=f"(lo), "=f"(hi) : "l"(acc0[oo]));
            y[((size_t)o * NLAT_O + t) * NLON_O + pA0] = lo + hi;
        }
        if (pA1 < 720) {
            asm("mov.b64 {%0,%1},%2;" : "=f"(lo), "=f"(hi) : "l"(acc1[oo]));
            y[((size_t)o * NLAT_O + t) * NLON_O + pA1] = lo + hi;
        }
    }
}

// ---------------- launcher ----------------
extern "C" void kernel_launch(void* const* d_in, const int* in_sizes, int n_in,
                              void* d_out, int out_size) {
    const float* x = (const float*)d_in[0];       // [1,32,240,480]
    const float* w = (const float*)d_in[1];       // [32,32,7]
    float* y = (float*)d_out;                     // [1,32,361,720]

    cudaFuncSetAttribute(conv_kernel, cudaFuncAttributeMaxDynamicSharedMemorySize, SMEM_C);

    int nA = CI * NLAT_O * NLON_O;
    upsample_kernel<<<(nA + 255) / 256, 256>>>(x);
    build_psi_kernel<<<dim3(21, 361), 256>>>();
    inv_kernel<<<(7 * 361 + 255) / 256, 256>>>();
    pack_kernel<<<(32 * 112 + 255) / 256, 256>>>(w);
    conv_kernel<<<dim3(12, 361), 256, SMEM_C>>>(y);
}